// round 1
// baseline (speedup 1.0000x reference)
#include <cuda_runtime.h>
#include <cuda_bf16.h>
#include <math.h>

// Problem constants
#define BATCH 8
#define CDIM  512      // QUERY_DIM == CROSS_DIM == INNER
#define NPIX  1024     // H*W
#define HEADS 8
#define HDIM  64

// Scratch: q, k, v, attn_out  each [B, 512, 1024] fp32
__device__ float g_q[BATCH * CDIM * NPIX];
__device__ float g_k[BATCH * CDIM * NPIX];
__device__ float g_v[BATCH * CDIM * NPIX];
__device__ float g_att[BATCH * CDIM * NPIX];

// ---------------------------------------------------------------------------
// SGEMM: C[b,m,n] = sum_k A[m,k] * X[b,k,n] + bias[m] (+ res[b,m,n])
// M=512, K=512, N=1024. Tile 128x128x8, 256 threads, 8x8 per thread.
// ---------------------------------------------------------------------------
__global__ __launch_bounds__(256) void sgemm_proj(
    const float* __restrict__ A,     // [512 x 512] row-major
    const float* __restrict__ X,     // [B x 512 x 1024]
    const float* __restrict__ bias,  // [512]
    const float* __restrict__ res,   // optional [B x 512 x 1024] or null
    float* __restrict__ C)           // [B x 512 x 1024]
{
    const int M = 512, K = 512, N = 1024;
    const int b  = blockIdx.z;
    const int m0 = blockIdx.y * 128;
    const int n0 = blockIdx.x * 128;
    const float* Xb = X + (size_t)b * K * N;

    __shared__ float As[8][132];   // pad 132: conflict-free stores & loads
    __shared__ float Bs[8][128];

    const int tid = threadIdx.x;
    const int tx  = tid & 15;      // n direction
    const int ty  = tid >> 4;      // m direction

    float acc[8][8];
#pragma unroll
    for (int i = 0; i < 8; i++)
#pragma unroll
        for (int j = 0; j < 8; j++) acc[i][j] = 0.f;

    for (int k0 = 0; k0 < K; k0 += 8) {
        // A tile: 128 rows x 8 k  (k fastest -> coalesced-ish global reads)
#pragma unroll
        for (int l = 0; l < 4; l++) {
            int i  = l * 256 + tid;       // 0..1023
            int m  = i >> 3;
            int kk = i & 7;
            As[kk][m] = A[(size_t)(m0 + m) * K + k0 + kk];
        }
        // B tile: 8 k x 128 n (n fastest -> fully coalesced)
#pragma unroll
        for (int l = 0; l < 4; l++) {
            int i  = l * 256 + tid;
            int kk = i >> 7;
            int n  = i & 127;
            Bs[kk][n] = Xb[(size_t)(k0 + kk) * N + n0 + n];
        }
        __syncthreads();

#pragma unroll
        for (int kk = 0; kk < 8; kk++) {
            float a[8], bb[8];
#pragma unroll
            for (int i = 0; i < 8; i++) a[i] = As[kk][ty + 16 * i];
#pragma unroll
            for (int j = 0; j < 8; j++) bb[j] = Bs[kk][tx + 16 * j];
#pragma unroll
            for (int i = 0; i < 8; i++)
#pragma unroll
                for (int j = 0; j < 8; j++)
                    acc[i][j] += a[i] * bb[j];
        }
        __syncthreads();
    }

    // Epilogue
#pragma unroll
    for (int i = 0; i < 8; i++) {
        const int m = m0 + ty + 16 * i;
        const float bv = bias[m];
        const size_t rowbase = (size_t)b * M * N + (size_t)m * N;
#pragma unroll
        for (int j = 0; j < 8; j++) {
            const int n = n0 + tx + 16 * j;
            float v = acc[i][j] + bv;
            if (res) v += res[rowbase + n];
            C[rowbase + n] = v;
        }
    }
}

// ---------------------------------------------------------------------------
// Flash attention: per (b,h), softmax(Q K^T / 8) V.
// Q/K/V layout: [b, h*64+d, n]  (channel-major). Output same layout.
// Block = 128 threads = 128 query rows. KV tile = 32 rows in smem.
// ---------------------------------------------------------------------------
__global__ __launch_bounds__(128) void flash_attn_kernel()
{
    const int N = 1024;
    const int b = blockIdx.z;
    const int h = blockIdx.y;
    const int n = blockIdx.x * 128 + threadIdx.x;   // this thread's query row
    const size_t base = ((size_t)b * CDIM + h * HDIM) * (size_t)N;

    // q row (pre-scaled by 1/sqrt(64))
    float q[HDIM];
#pragma unroll
    for (int d = 0; d < HDIM; d++)
        q[d] = g_q[base + (size_t)d * N + n] * 0.125f;

    __shared__ float Ks[32][68];   // pitch 68: 16B-aligned rows -> LDS.128
    __shared__ float Vs[32][68];

    float o[HDIM];
#pragma unroll
    for (int d = 0; d < HDIM; d++) o[d] = 0.f;
    float mcur = -1e30f;
    float lsum = 0.f;

    for (int m0 = 0; m0 < N; m0 += 32) {
        // Load K,V tile: 32 rows x 64 d; m fastest -> coalesced global
#pragma unroll
        for (int t = 0; t < 16; t++) {
            int i  = t * 128 + threadIdx.x;   // 0..2047
            int d  = i >> 5;
            int mm = i & 31;
            Ks[mm][d] = g_k[base + (size_t)d * N + m0 + mm];
            Vs[mm][d] = g_v[base + (size_t)d * N + m0 + mm];
        }
        __syncthreads();

        // scores for this tile
        float s[32];
#pragma unroll 4
        for (int j = 0; j < 32; j++) {
            float a0 = 0.f, a1 = 0.f, a2 = 0.f, a3 = 0.f;
#pragma unroll
            for (int d = 0; d < HDIM; d += 4) {
                const float4 kv = *(const float4*)&Ks[j][d];
                a0 += q[d + 0] * kv.x;
                a1 += q[d + 1] * kv.y;
                a2 += q[d + 2] * kv.z;
                a3 += q[d + 3] * kv.w;
            }
            s[j] = (a0 + a1) + (a2 + a3);
        }

        // online softmax update
        float tmax = s[0];
#pragma unroll
        for (int j = 1; j < 32; j++) tmax = fmaxf(tmax, s[j]);
        const float mnew = fmaxf(mcur, tmax);
        const float corr = __expf(mcur - mnew);
        lsum *= corr;
#pragma unroll
        for (int d = 0; d < HDIM; d++) o[d] *= corr;

#pragma unroll 4
        for (int j = 0; j < 32; j++) {
            const float p = __expf(s[j] - mnew);
            lsum += p;
#pragma unroll
            for (int d = 0; d < HDIM; d += 4) {
                const float4 vv = *(const float4*)&Vs[j][d];
                o[d + 0] += p * vv.x;
                o[d + 1] += p * vv.y;
                o[d + 2] += p * vv.z;
                o[d + 3] += p * vv.w;
            }
        }
        mcur = mnew;
        __syncthreads();
    }

    const float inv = 1.f / lsum;
#pragma unroll
    for (int d = 0; d < HDIM; d++)
        g_att[base + (size_t)d * N + n] = o[d] * inv;
}

// ---------------------------------------------------------------------------
extern "C" void kernel_launch(void* const* d_in, const int* in_sizes, int n_in,
                              void* d_out, int out_size)
{
    (void)in_sizes; (void)n_in; (void)out_size;
    const float* self_f  = (const float*)d_in[0];
    const float* cross_f = (const float*)d_in[1];
    const float* Wq   = (const float*)d_in[2];
    const float* bq   = (const float*)d_in[3];
    const float* Wk   = (const float*)d_in[4];
    const float* bk   = (const float*)d_in[5];
    const float* Wv   = (const float*)d_in[6];
    const float* bv   = (const float*)d_in[7];
    const float* Wout = (const float*)d_in[8];
    const float* bout = (const float*)d_in[9];
    float* out = (float*)d_out;

    float *gq, *gk, *gv, *ga;
    cudaGetSymbolAddress((void**)&gq, g_q);
    cudaGetSymbolAddress((void**)&gk, g_k);
    cudaGetSymbolAddress((void**)&gv, g_v);
    cudaGetSymbolAddress((void**)&ga, g_att);

    dim3 gemmGrid(NPIX / 128, CDIM / 128, BATCH);  // (8,4,8)
    dim3 gemmBlk(256);

    sgemm_proj<<<gemmGrid, gemmBlk>>>(Wq, self_f,  bq, nullptr, gq);
    sgemm_proj<<<gemmGrid, gemmBlk>>>(Wk, cross_f, bk, nullptr, gk);
    sgemm_proj<<<gemmGrid, gemmBlk>>>(Wv, cross_f, bv, nullptr, gv);

    dim3 attnGrid(NPIX / 128, HEADS, BATCH);       // (8,8,8)
    flash_attn_kernel<<<attnGrid, 128>>>();

    sgemm_proj<<<gemmGrid, gemmBlk>>>(Wout, ga, bout, self_f, out);
}

// round 3
// speedup vs baseline: 1.2883x; 1.2883x over previous
#include <cuda_runtime.h>
#include <cuda_bf16.h>
#include <math.h>
#include <stdint.h>

// Problem constants
#define BATCH 8
#define CDIM  512      // QUERY_DIM == CROSS_DIM == INNER
#define NPIX  1024     // H*W
#define HEADS 8
#define HDIM  64

// Scratch: q, k, v, attn_out  each [B, 512, 1024] fp32
__device__ float g_q[BATCH * CDIM * NPIX];
__device__ float g_k[BATCH * CDIM * NPIX];
__device__ float g_v[BATCH * CDIM * NPIX];
__device__ float g_att[BATCH * CDIM * NPIX];

__device__ __forceinline__ uint32_t f2tf32(float v) {
    uint32_t r;
    asm("cvt.rna.tf32.f32 %0, %1;" : "=r"(r) : "f"(v));
    return r;
}

__device__ __forceinline__ void mma_tf32(float c[4], const uint32_t a[4], const uint32_t b[2]) {
    asm volatile(
        "mma.sync.aligned.m16n8k8.row.col.f32.tf32.tf32.f32 "
        "{%0,%1,%2,%3}, {%4,%5,%6,%7}, {%8,%9}, {%0,%1,%2,%3};"
        : "+f"(c[0]), "+f"(c[1]), "+f"(c[2]), "+f"(c[3])
        : "r"(a[0]), "r"(a[1]), "r"(a[2]), "r"(a[3]), "r"(b[0]), "r"(b[1]));
}

// ---------------------------------------------------------------------------
// TF32 tensor-core GEMM: C[b,m,n] = sum_k A[m,k] * X[b,k,n] + bias[m] (+res)
// M=512, K=512, N=1024. Block tile 128x128x16, 256 thr = 8 warps (2m x 4n),
// warp tile 64x32 = 4x4 m16n8k8 mma tiles.
// ---------------------------------------------------------------------------
#define PADA 136   // smem k-row stride (floats); 136%32=8 -> conflict-free frags
#define PADB 136

__global__ __launch_bounds__(256) void mma_proj(
    const float* __restrict__ A,     // [512 x 512] row-major
    const float* __restrict__ X,     // [B x 512 x 1024]
    const float* __restrict__ bias,  // [512]
    const float* __restrict__ res,   // optional [B x 512 x 1024] or null
    float* __restrict__ C)           // [B x 512 x 1024]
{
    const int M = 512, K = 512, N = 1024;
    const int b  = blockIdx.z;
    const int m0 = blockIdx.y * 128;
    const int n0 = blockIdx.x * 128;
    const float* Xb = X + (size_t)b * K * N;

    __shared__ uint32_t As[16 * PADA];   // As[k][m]
    __shared__ uint32_t Bs[16 * PADB];   // Bs[k][n]

    const int tid  = threadIdx.x;
    const int lane = tid & 31;
    const int wid  = tid >> 5;
    const int wm   = (wid >> 2) * 64;   // warp m offset in tile
    const int wn   = (wid & 3) * 32;    // warp n offset in tile

    const int grp = lane >> 2;  // 0..7
    const int qid = lane & 3;   // 0..3

    float acc[4][4][4];
#pragma unroll
    for (int i = 0; i < 4; i++)
#pragma unroll
        for (int j = 0; j < 4; j++)
#pragma unroll
            for (int r = 0; r < 4; r++) acc[i][j][r] = 0.f;

    for (int k0 = 0; k0 < K; k0 += 16) {
        // ---- load A tile: 128 m x 16 k. thread -> (m = idx&127, kq = idx>>7)
#pragma unroll
        for (int l = 0; l < 2; l++) {
            int idx = l * 256 + tid;
            int m   = idx & 127;
            int kq  = idx >> 7;              // 0..3 -> k block of 4
            float4 v = *(const float4*)(A + (size_t)(m0 + m) * K + k0 + kq * 4);
            As[(kq * 4 + 0) * PADA + m] = f2tf32(v.x);
            As[(kq * 4 + 1) * PADA + m] = f2tf32(v.y);
            As[(kq * 4 + 2) * PADA + m] = f2tf32(v.z);
            As[(kq * 4 + 3) * PADA + m] = f2tf32(v.w);
        }
        // ---- load B tile: 16 k x 128 n. thread -> (kk = idx>>5, nq = idx&31)
#pragma unroll
        for (int l = 0; l < 2; l++) {
            int idx = l * 256 + tid;
            int kk  = idx >> 5;              // 0..15
            int nq  = idx & 31;              // float4 column group
            float4 v = *(const float4*)(Xb + (size_t)(k0 + kk) * N + n0 + nq * 4);
            uint4 t;
            t.x = f2tf32(v.x); t.y = f2tf32(v.y);
            t.z = f2tf32(v.z); t.w = f2tf32(v.w);
            *(uint4*)&Bs[kk * PADB + nq * 4] = t;   // STS.128, conflict-free
        }
        __syncthreads();

#pragma unroll
        for (int ks = 0; ks < 16; ks += 8) {
            uint32_t af[4][4];
#pragma unroll
            for (int mt = 0; mt < 4; mt++) {
                int mr = wm + mt * 16 + grp;
                int kc = ks + qid;
                af[mt][0] = As[kc * PADA + mr];
                af[mt][1] = As[kc * PADA + mr + 8];
                af[mt][2] = As[(kc + 4) * PADA + mr];
                af[mt][3] = As[(kc + 4) * PADA + mr + 8];
            }
            uint32_t bf[4][2];
#pragma unroll
            for (int nt = 0; nt < 4; nt++) {
                int nc = wn + nt * 8 + grp;
                int kr = ks + qid;
                bf[nt][0] = Bs[kr * PADB + nc];
                bf[nt][1] = Bs[(kr + 4) * PADB + nc];
            }
#pragma unroll
            for (int mt = 0; mt < 4; mt++)
#pragma unroll
                for (int nt = 0; nt < 4; nt++)
                    mma_tf32(acc[mt][nt], af[mt], bf[nt]);
        }
        __syncthreads();
    }

    // ---- epilogue: c0 at (grp, 2*qid), c1 +1 col, c2/c3 at row+8
#pragma unroll
    for (int mt = 0; mt < 4; mt++) {
        const int r0 = m0 + wm + mt * 16 + grp;
        const int r1 = r0 + 8;
        const float bv0 = bias[r0];
        const float bv1 = bias[r1];
        const size_t rb0 = (size_t)b * M * N + (size_t)r0 * N;
        const size_t rb1 = (size_t)b * M * N + (size_t)r1 * N;
#pragma unroll
        for (int nt = 0; nt < 4; nt++) {
            const int col = n0 + wn + nt * 8 + 2 * qid;
            float2 v0 = make_float2(acc[mt][nt][0] + bv0, acc[mt][nt][1] + bv0);
            float2 v1 = make_float2(acc[mt][nt][2] + bv1, acc[mt][nt][3] + bv1);
            if (res) {
                const float2 q0 = *(const float2*)(res + rb0 + col);
                const float2 q1 = *(const float2*)(res + rb1 + col);
                v0.x += q0.x; v0.y += q0.y;
                v1.x += q1.x; v1.y += q1.y;
            }
            *(float2*)(C + rb0 + col) = v0;
            *(float2*)(C + rb1 + col) = v1;
        }
    }
}

// ---------------------------------------------------------------------------
// Flash attention: per (b,h), softmax(Q K^T / 8) V.
// Q/K/V layout: [b, h*64+d, n]  (channel-major). Output same layout.
// Block = 128 threads = 128 query rows. KV tile = 32 rows in smem.
// ---------------------------------------------------------------------------
__global__ __launch_bounds__(128) void flash_attn_kernel()
{
    const int N = 1024;
    const int b = blockIdx.z;
    const int h = blockIdx.y;
    const int n = blockIdx.x * 128 + threadIdx.x;   // this thread's query row
    const size_t base = ((size_t)b * CDIM + h * HDIM) * (size_t)N;

    // q row (pre-scaled by 1/sqrt(64))
    float q[HDIM];
#pragma unroll
    for (int d = 0; d < HDIM; d++)
        q[d] = g_q[base + (size_t)d * N + n] * 0.125f;

    __shared__ float Ks[32][68];   // pitch 68: 16B-aligned rows -> LDS.128
    __shared__ float Vs[32][68];

    float o[HDIM];
#pragma unroll
    for (int d = 0; d < HDIM; d++) o[d] = 0.f;
    float mcur = -1e30f;
    float lsum = 0.f;

    for (int m0 = 0; m0 < N; m0 += 32) {
        // Load K,V tile: 32 rows x 64 d; m fastest -> coalesced global
#pragma unroll
        for (int t = 0; t < 16; t++) {
            int i  = t * 128 + threadIdx.x;   // 0..2047
            int d  = i >> 5;
            int mm = i & 31;
            Ks[mm][d] = g_k[base + (size_t)d * N + m0 + mm];
            Vs[mm][d] = g_v[base + (size_t)d * N + m0 + mm];
        }
        __syncthreads();

        // scores for this tile
        float s[32];
#pragma unroll 4
        for (int j = 0; j < 32; j++) {
            float a0 = 0.f, a1 = 0.f, a2 = 0.f, a3 = 0.f;
#pragma unroll
            for (int d = 0; d < HDIM; d += 4) {
                const float4 kv = *(const float4*)&Ks[j][d];
                a0 += q[d + 0] * kv.x;
                a1 += q[d + 1] * kv.y;
                a2 += q[d + 2] * kv.z;
                a3 += q[d + 3] * kv.w;
            }
            s[j] = (a0 + a1) + (a2 + a3);
        }

        // online softmax update
        float tmax = s[0];
#pragma unroll
        for (int j = 1; j < 32; j++) tmax = fmaxf(tmax, s[j]);
        const float mnew = fmaxf(mcur, tmax);
        const float corr = __expf(mcur - mnew);
        lsum *= corr;
#pragma unroll
        for (int d = 0; d < HDIM; d++) o[d] *= corr;

#pragma unroll 4
        for (int j = 0; j < 32; j++) {
            const float p = __expf(s[j] - mnew);
            lsum += p;
#pragma unroll
            for (int d = 0; d < HDIM; d += 4) {
                const float4 vv = *(const float4*)&Vs[j][d];
                o[d + 0] += p * vv.x;
                o[d + 1] += p * vv.y;
                o[d + 2] += p * vv.z;
                o[d + 3] += p * vv.w;
            }
        }
        mcur = mnew;
        __syncthreads();
    }

    const float inv = 1.f / lsum;
#pragma unroll
    for (int d = 0; d < HDIM; d++)
        g_att[base + (size_t)d * N + n] = o[d] * inv;
}

// ---------------------------------------------------------------------------
extern "C" void kernel_launch(void* const* d_in, const int* in_sizes, int n_in,
                              void* d_out, int out_size)
{
    (void)in_sizes; (void)n_in; (void)out_size;
    const float* self_f  = (const float*)d_in[0];
    const float* cross_f = (const float*)d_in[1];
    const float* Wq   = (const float*)d_in[2];
    const float* bq   = (const float*)d_in[3];
    const float* Wk   = (const float*)d_in[4];
    const float* bk   = (const float*)d_in[5];
    const float* Wv   = (const float*)d_in[6];
    const float* bv   = (const float*)d_in[7];
    const float* Wout = (const float*)d_in[8];
    const float* bout = (const float*)d_in[9];
    float* out = (float*)d_out;

    float *gq, *gk, *gv, *ga;
    cudaGetSymbolAddress((void**)&gq, g_q);
    cudaGetSymbolAddress((void**)&gk, g_k);
    cudaGetSymbolAddress((void**)&gv, g_v);
    cudaGetSymbolAddress((void**)&ga, g_att);

    dim3 gemmGrid(NPIX / 128, CDIM / 128, BATCH);  // (8,4,8)
    dim3 gemmBlk(256);

    mma_proj<<<gemmGrid, gemmBlk>>>(Wq, self_f,  bq, nullptr, gq);
    mma_proj<<<gemmGrid, gemmBlk>>>(Wk, cross_f, bk, nullptr, gk);
    mma_proj<<<gemmGrid, gemmBlk>>>(Wv, cross_f, bv, nullptr, gv);

    dim3 attnGrid(NPIX / 128, HEADS, BATCH);       // (8,8,8)
    flash_attn_kernel<<<attnGrid, 128>>>();

    mma_proj<<<gemmGrid, gemmBlk>>>(Wout, ga, bout, self_f, out);
}

// round 4
// speedup vs baseline: 3.7102x; 2.8798x over previous
#include <cuda_runtime.h>
#include <cuda_bf16.h>
#include <math.h>
#include <stdint.h>

// Problem constants
#define BATCH 8
#define CDIM  512      // QUERY_DIM == CROSS_DIM == INNER
#define NPIX  1024     // H*W
#define HEADS 8
#define HDIM  64

// Scratch: q, k, v, attn_out  each [B, 512, 1024] fp32
__device__ float g_q[BATCH * CDIM * NPIX];
__device__ float g_k[BATCH * CDIM * NPIX];
__device__ float g_v[BATCH * CDIM * NPIX];
__device__ float g_att[BATCH * CDIM * NPIX];

__device__ __forceinline__ uint32_t f2tf32(float v) {
    uint32_t r;
    asm("cvt.rna.tf32.f32 %0, %1;" : "=r"(r) : "f"(v));
    return r;
}

__device__ __forceinline__ void mma_tf32(float c[4], const uint32_t a[4], const uint32_t b[2]) {
    asm volatile(
        "mma.sync.aligned.m16n8k8.row.col.f32.tf32.tf32.f32 "
        "{%0,%1,%2,%3}, {%4,%5,%6,%7}, {%8,%9}, {%0,%1,%2,%3};"
        : "+f"(c[0]), "+f"(c[1]), "+f"(c[2]), "+f"(c[3])
        : "r"(a[0]), "r"(a[1]), "r"(a[2]), "r"(a[3]), "r"(b[0]), "r"(b[1]));
}

// ---------------------------------------------------------------------------
// TF32 tensor-core GEMM: C[b,m,n] = sum_k A[m,k] * X[b,k,n] + bias[m] (+res)
// ---------------------------------------------------------------------------
#define PADA 136
#define PADB 136

__global__ __launch_bounds__(256) void mma_proj(
    const float* __restrict__ A,
    const float* __restrict__ X,
    const float* __restrict__ bias,
    const float* __restrict__ res,
    float* __restrict__ C)
{
    const int M = 512, K = 512, N = 1024;
    const int b  = blockIdx.z;
    const int m0 = blockIdx.y * 128;
    const int n0 = blockIdx.x * 128;
    const float* Xb = X + (size_t)b * K * N;

    __shared__ uint32_t As[16 * PADA];
    __shared__ uint32_t Bs[16 * PADB];

    const int tid  = threadIdx.x;
    const int lane = tid & 31;
    const int wid  = tid >> 5;
    const int wm   = (wid >> 2) * 64;
    const int wn   = (wid & 3) * 32;
    const int grp = lane >> 2;
    const int qid = lane & 3;

    float acc[4][4][4];
#pragma unroll
    for (int i = 0; i < 4; i++)
#pragma unroll
        for (int j = 0; j < 4; j++)
#pragma unroll
            for (int r = 0; r < 4; r++) acc[i][j][r] = 0.f;

    for (int k0 = 0; k0 < K; k0 += 16) {
#pragma unroll
        for (int l = 0; l < 2; l++) {
            int idx = l * 256 + tid;
            int m   = idx & 127;
            int kq  = idx >> 7;
            float4 v = *(const float4*)(A + (size_t)(m0 + m) * K + k0 + kq * 4);
            As[(kq * 4 + 0) * PADA + m] = f2tf32(v.x);
            As[(kq * 4 + 1) * PADA + m] = f2tf32(v.y);
            As[(kq * 4 + 2) * PADA + m] = f2tf32(v.z);
            As[(kq * 4 + 3) * PADA + m] = f2tf32(v.w);
        }
#pragma unroll
        for (int l = 0; l < 2; l++) {
            int idx = l * 256 + tid;
            int kk  = idx >> 5;
            int nq  = idx & 31;
            float4 v = *(const float4*)(Xb + (size_t)(k0 + kk) * N + n0 + nq * 4);
            uint4 t;
            t.x = f2tf32(v.x); t.y = f2tf32(v.y);
            t.z = f2tf32(v.z); t.w = f2tf32(v.w);
            *(uint4*)&Bs[kk * PADB + nq * 4] = t;
        }
        __syncthreads();

#pragma unroll
        for (int ks = 0; ks < 16; ks += 8) {
            uint32_t af[4][4];
#pragma unroll
            for (int mt = 0; mt < 4; mt++) {
                int mr = wm + mt * 16 + grp;
                int kc = ks + qid;
                af[mt][0] = As[kc * PADA + mr];
                af[mt][1] = As[kc * PADA + mr + 8];
                af[mt][2] = As[(kc + 4) * PADA + mr];
                af[mt][3] = As[(kc + 4) * PADA + mr + 8];
            }
            uint32_t bf[4][2];
#pragma unroll
            for (int nt = 0; nt < 4; nt++) {
                int nc = wn + nt * 8 + grp;
                int kr = ks + qid;
                bf[nt][0] = Bs[kr * PADB + nc];
                bf[nt][1] = Bs[(kr + 4) * PADB + nc];
            }
#pragma unroll
            for (int mt = 0; mt < 4; mt++)
#pragma unroll
                for (int nt = 0; nt < 4; nt++)
                    mma_tf32(acc[mt][nt], af[mt], bf[nt]);
        }
        __syncthreads();
    }

#pragma unroll
    for (int mt = 0; mt < 4; mt++) {
        const int r0 = m0 + wm + mt * 16 + grp;
        const int r1 = r0 + 8;
        const float bv0 = bias[r0];
        const float bv1 = bias[r1];
        const size_t rb0 = (size_t)b * M * N + (size_t)r0 * N;
        const size_t rb1 = (size_t)b * M * N + (size_t)r1 * N;
#pragma unroll
        for (int nt = 0; nt < 4; nt++) {
            const int col = n0 + wn + nt * 8 + 2 * qid;
            float2 v0 = make_float2(acc[mt][nt][0] + bv0, acc[mt][nt][1] + bv0);
            float2 v1 = make_float2(acc[mt][nt][2] + bv1, acc[mt][nt][3] + bv1);
            if (res) {
                const float2 q0 = *(const float2*)(res + rb0 + col);
                const float2 q1 = *(const float2*)(res + rb1 + col);
                v0.x += q0.x; v0.y += q0.y;
                v1.x += q1.x; v1.y += q1.y;
            }
            *(float2*)(C + rb0 + col) = v0;
            *(float2*)(C + rb1 + col) = v1;
        }
    }
}

// ---------------------------------------------------------------------------
// TF32 tensor-core flash attention.
// Per (b,h): O = softmax(Q K^T / 8) V, computed as O^T = V^T P^T so that all
// operands and the output live in the channel-major [d][n] scratch layout.
// CTA: 128 q-rows, 8 warps x 16 rows. K-tile = 64 keys.
//  S-mma : A = Q rows (regs), B = K from smem [d][m]   -> S c-frags
//  PV-mma: A = V^T from smem [d][m], B = P via shuffles -> O^T c-frags
// ---------------------------------------------------------------------------
#define KST 76   // smem row stride: banks (12*q+g) and (12*g+q) both bijective

__global__ __launch_bounds__(256) void flash_mma_kernel()
{
    const int N = 1024;
    const int b = blockIdx.z;
    const int h = blockIdx.y;
    const int tid  = threadIdx.x;
    const int lane = tid & 31;
    const int w    = tid >> 5;
    const int grp  = lane >> 2;
    const int qid  = lane & 3;
    const size_t base = ((size_t)b * CDIM + h * HDIM) * (size_t)N;
    const int q0 = blockIdx.x * 128 + w * 16;   // this warp's q rows

    __shared__ uint32_t Ks[64 * KST];
    __shared__ uint32_t Vs[64 * KST];

    // ---- Q A-fragments (scaled by 1/8), kept in registers for all tiles
    uint32_t qa[8][4];
#pragma unroll
    for (int kc = 0; kc < 8; kc++) {
        const int d0 = qid + 8 * kc;
        const int r0 = q0 + grp;
        qa[kc][0] = f2tf32(g_q[base + (size_t)d0 * N + r0] * 0.125f);
        qa[kc][1] = f2tf32(g_q[base + (size_t)d0 * N + r0 + 8] * 0.125f);
        qa[kc][2] = f2tf32(g_q[base + (size_t)(d0 + 4) * N + r0] * 0.125f);
        qa[kc][3] = f2tf32(g_q[base + (size_t)(d0 + 4) * N + r0 + 8] * 0.125f);
    }

    float o[4][2][4];
#pragma unroll
    for (int it = 0; it < 4; it++)
#pragma unroll
        for (int j = 0; j < 2; j++)
#pragma unroll
            for (int r = 0; r < 4; r++) o[it][j][r] = 0.f;
    float m0 = -1e30f, m1 = -1e30f, l0 = 0.f, l1 = 0.f;

    for (int t0 = 0; t0 < N; t0 += 64) {
        // ---- stage K, V tiles: [64 d][64 m], direct copy (channel-major)
#pragma unroll
        for (int it = 0; it < 16; it++) {
            int i  = it * 256 + tid;
            int d  = i >> 6;
            int mm = i & 63;
            Ks[d * KST + mm] = f2tf32(g_k[base + (size_t)d * N + t0 + mm]);
            Vs[d * KST + mm] = f2tf32(g_v[base + (size_t)d * N + t0 + mm]);
        }
        __syncthreads();

        // ---- S = Q K^T : 8 n-tiles (keys) x 8 k-chunks (d)
        float s[8][4];
#pragma unroll
        for (int nt = 0; nt < 8; nt++) {
            s[nt][0] = s[nt][1] = s[nt][2] = s[nt][3] = 0.f;
#pragma unroll
            for (int kc = 0; kc < 8; kc++) {
                uint32_t bf[2];
                bf[0] = Ks[(kc * 8 + qid) * KST + nt * 8 + grp];
                bf[1] = Ks[(kc * 8 + qid + 4) * KST + nt * 8 + grp];
                mma_tf32(s[nt], qa[kc], bf);
            }
        }

        // ---- online softmax (rows grp / grp+8, reduced across the quad)
        float t_0 = -1e30f, t_1 = -1e30f;
#pragma unroll
        for (int nt = 0; nt < 8; nt++) {
            t_0 = fmaxf(t_0, fmaxf(s[nt][0], s[nt][1]));
            t_1 = fmaxf(t_1, fmaxf(s[nt][2], s[nt][3]));
        }
        t_0 = fmaxf(t_0, __shfl_xor_sync(0xffffffffu, t_0, 1));
        t_0 = fmaxf(t_0, __shfl_xor_sync(0xffffffffu, t_0, 2));
        t_1 = fmaxf(t_1, __shfl_xor_sync(0xffffffffu, t_1, 1));
        t_1 = fmaxf(t_1, __shfl_xor_sync(0xffffffffu, t_1, 2));
        const float nm0 = fmaxf(m0, t_0);
        const float nm1 = fmaxf(m1, t_1);
        const float corr0 = __expf(m0 - nm0);
        const float corr1 = __expf(m1 - nm1);
        m0 = nm0; m1 = nm1;

        uint32_t pu[8][4];
        float rs0 = 0.f, rs1 = 0.f;
#pragma unroll
        for (int nt = 0; nt < 8; nt++) {
            float p0 = __expf(s[nt][0] - nm0);
            float p1 = __expf(s[nt][1] - nm0);
            float p2 = __expf(s[nt][2] - nm1);
            float p3 = __expf(s[nt][3] - nm1);
            rs0 += p0 + p1;
            rs1 += p2 + p3;
            pu[nt][0] = f2tf32(p0); pu[nt][1] = f2tf32(p1);
            pu[nt][2] = f2tf32(p2); pu[nt][3] = f2tf32(p3);
        }
        rs0 += __shfl_xor_sync(0xffffffffu, rs0, 1);
        rs0 += __shfl_xor_sync(0xffffffffu, rs0, 2);
        rs1 += __shfl_xor_sync(0xffffffffu, rs1, 1);
        rs1 += __shfl_xor_sync(0xffffffffu, rs1, 2);
        l0 = l0 * corr0 + rs0;
        l1 = l1 * corr1 + rs1;

        // ---- rescale O^T frags (cols are q rows; fetch corr of col owners)
        const float cA0 = __shfl_sync(0xffffffffu, corr0, 8 * qid);
        const float cA1 = __shfl_sync(0xffffffffu, corr0, 8 * qid + 4);
        const float cB0 = __shfl_sync(0xffffffffu, corr1, 8 * qid);
        const float cB1 = __shfl_sync(0xffffffffu, corr1, 8 * qid + 4);
#pragma unroll
        for (int it = 0; it < 4; it++) {
            o[it][0][0] *= cA0; o[it][0][1] *= cA1;
            o[it][0][2] *= cA0; o[it][0][3] *= cA1;
            o[it][1][0] *= cB0; o[it][1][1] *= cB1;
            o[it][1][2] *= cB0; o[it][1][3] *= cB1;
        }

        // ---- O^T += V^T P^T : per k-chunk build P B-frags via shuffles
        const int srcA = (lane & ~3) | (qid >> 1);
        const int srcB = srcA + 2;
#pragma unroll
        for (int kc = 0; kc < 8; kc++) {
            uint32_t pA0 = __shfl_sync(0xffffffffu, pu[kc][0], srcA);
            uint32_t pA1 = __shfl_sync(0xffffffffu, pu[kc][1], srcA);
            uint32_t pA2 = __shfl_sync(0xffffffffu, pu[kc][2], srcA);
            uint32_t pA3 = __shfl_sync(0xffffffffu, pu[kc][3], srcA);
            uint32_t pB0 = __shfl_sync(0xffffffffu, pu[kc][0], srcB);
            uint32_t pB1 = __shfl_sync(0xffffffffu, pu[kc][1], srcB);
            uint32_t pB2 = __shfl_sync(0xffffffffu, pu[kc][2], srcB);
            uint32_t pB3 = __shfl_sync(0xffffffffu, pu[kc][3], srcB);
            uint32_t bj0[2], bj1[2];
            bj0[0] = (qid & 1) ? pA1 : pA0;
            bj0[1] = (qid & 1) ? pB1 : pB0;
            bj1[0] = (qid & 1) ? pA3 : pA2;
            bj1[1] = (qid & 1) ? pB3 : pB2;
#pragma unroll
            for (int it = 0; it < 4; it++) {
                const int r = it * 16 + grp;
                uint32_t af[4];
                af[0] = Vs[r * KST + kc * 8 + qid];
                af[1] = Vs[(r + 8) * KST + kc * 8 + qid];
                af[2] = Vs[r * KST + kc * 8 + qid + 4];
                af[3] = Vs[(r + 8) * KST + kc * 8 + qid + 4];
                mma_tf32(o[it][0], af, bj0);
                mma_tf32(o[it][1], af, bj1);
            }
        }
        __syncthreads();
    }

    // ---- epilogue: divide by l (per q-col), store O^T into [d][n] layout
    const float lA0 = __shfl_sync(0xffffffffu, l0, 8 * qid);
    const float lA1 = __shfl_sync(0xffffffffu, l0, 8 * qid + 4);
    const float lB0 = __shfl_sync(0xffffffffu, l1, 8 * qid);
    const float lB1 = __shfl_sync(0xffffffffu, l1, 8 * qid + 4);
    const float iA0 = 1.f / lA0, iA1 = 1.f / lA1;
    const float iB0 = 1.f / lB0, iB1 = 1.f / lB1;
    const int nc0 = blockIdx.x * 128 + w * 16 + 2 * qid;
#pragma unroll
    for (int it = 0; it < 4; it++) {
        const int d0 = it * 16 + grp;
        float2 v;
        v.x = o[it][0][0] * iA0; v.y = o[it][0][1] * iA1;
        *(float2*)&g_att[base + (size_t)d0 * N + nc0] = v;
        v.x = o[it][0][2] * iA0; v.y = o[it][0][3] * iA1;
        *(float2*)&g_att[base + (size_t)(d0 + 8) * N + nc0] = v;
        v.x = o[it][1][0] * iB0; v.y = o[it][1][1] * iB1;
        *(float2*)&g_att[base + (size_t)d0 * N + nc0 + 8] = v;
        v.x = o[it][1][2] * iB0; v.y = o[it][1][3] * iB1;
        *(float2*)&g_att[base + (size_t)(d0 + 8) * N + nc0 + 8] = v;
    }
}

// ---------------------------------------------------------------------------
extern "C" void kernel_launch(void* const* d_in, const int* in_sizes, int n_in,
                              void* d_out, int out_size)
{
    (void)in_sizes; (void)n_in; (void)out_size;
    const float* self_f  = (const float*)d_in[0];
    const float* cross_f = (const float*)d_in[1];
    const float* Wq   = (const float*)d_in[2];
    const float* bq   = (const float*)d_in[3];
    const float* Wk   = (const float*)d_in[4];
    const float* bk   = (const float*)d_in[5];
    const float* Wv   = (const float*)d_in[6];
    const float* bv   = (const float*)d_in[7];
    const float* Wout = (const float*)d_in[8];
    const float* bout = (const float*)d_in[9];
    float* out = (float*)d_out;

    float *gq, *gk, *gv, *ga;
    cudaGetSymbolAddress((void**)&gq, g_q);
    cudaGetSymbolAddress((void**)&gk, g_k);
    cudaGetSymbolAddress((void**)&gv, g_v);
    cudaGetSymbolAddress((void**)&ga, g_att);

    dim3 gemmGrid(NPIX / 128, CDIM / 128, BATCH);  // (8,4,8)
    dim3 gemmBlk(256);

    mma_proj<<<gemmGrid, gemmBlk>>>(Wq, self_f,  bq, nullptr, gq);
    mma_proj<<<gemmGrid, gemmBlk>>>(Wk, cross_f, bk, nullptr, gk);
    mma_proj<<<gemmGrid, gemmBlk>>>(Wv, cross_f, bv, nullptr, gv);

    dim3 attnGrid(NPIX / 128, HEADS, BATCH);       // (8,8,8)
    flash_mma_kernel<<<attnGrid, 256>>>();

    mma_proj<<<gemmGrid, gemmBlk>>>(Wout, ga, bout, self_f, out);
}

// round 6
// speedup vs baseline: 4.4170x; 1.1905x over previous
#include <cuda_runtime.h>
#include <cuda_bf16.h>
#include <math.h>
#include <stdint.h>

// Problem constants
#define BATCH 8
#define CDIM  512      // QUERY_DIM == CROSS_DIM == INNER
#define NPIX  1024     // H*W
#define HEADS 8
#define HDIM  64

// Scratch: q, k, v, attn_out  each [B, 512, 1024] fp32
__device__ float g_q[BATCH * CDIM * NPIX];
__device__ float g_k[BATCH * CDIM * NPIX];
__device__ float g_v[BATCH * CDIM * NPIX];
__device__ float g_att[BATCH * CDIM * NPIX];

__device__ __forceinline__ uint32_t f2tf32(float v) {
    uint32_t r;
    asm("cvt.rna.tf32.f32 %0, %1;" : "=r"(r) : "f"(v));
    return r;
}

__device__ __forceinline__ void mma_tf32(float c[4], const uint32_t a[4], const uint32_t b[2]) {
    asm volatile(
        "mma.sync.aligned.m16n8k8.row.col.f32.tf32.tf32.f32 "
        "{%0,%1,%2,%3}, {%4,%5,%6,%7}, {%8,%9}, {%0,%1,%2,%3};"
        : "+f"(c[0]), "+f"(c[1]), "+f"(c[2]), "+f"(c[3])
        : "r"(a[0]), "r"(a[1]), "r"(a[2]), "r"(a[3]), "r"(b[0]), "r"(b[1]));
}

__device__ __forceinline__ void cp16(uint32_t saddr, const void* gptr) {
    asm volatile("cp.async.ca.shared.global [%0], [%1], 16;" :: "r"(saddr), "l"(gptr));
}
__device__ __forceinline__ void cp_commit_wait() {
    asm volatile("cp.async.commit_group;");
    asm volatile("cp.async.wait_group 0;" ::: "memory");
}

// ---------------------------------------------------------------------------
// TF32 tensor-core GEMM: C[b,m,n] = sum_k A[m,k] * X[b,k,n] + bias[m] (+res)
// ---------------------------------------------------------------------------
#define PADA 136
#define PADB 136

__device__ __forceinline__ void mma_proj_body(
    const float* __restrict__ A,
    const float* __restrict__ X,
    const float* __restrict__ bias,
    const float* __restrict__ res,
    float* __restrict__ C,
    int b, int m0, int n0)
{
    const int M = 512, K = 512, N = 1024;
    const float* Xb = X + (size_t)b * K * N;

    __shared__ uint32_t As[16 * PADA];
    __shared__ uint32_t Bs[16 * PADB];

    const int tid  = threadIdx.x;
    const int lane = tid & 31;
    const int wid  = tid >> 5;
    const int wm   = (wid >> 2) * 64;
    const int wn   = (wid & 3) * 32;
    const int grp = lane >> 2;
    const int qid = lane & 3;

    float acc[4][4][4];
#pragma unroll
    for (int i = 0; i < 4; i++)
#pragma unroll
        for (int j = 0; j < 4; j++)
#pragma unroll
            for (int r = 0; r < 4; r++) acc[i][j][r] = 0.f;

    for (int k0 = 0; k0 < K; k0 += 16) {
#pragma unroll
        for (int l = 0; l < 2; l++) {
            int idx = l * 256 + tid;
            int m   = idx & 127;
            int kq  = idx >> 7;
            float4 v = *(const float4*)(A + (size_t)(m0 + m) * K + k0 + kq * 4);
            As[(kq * 4 + 0) * PADA + m] = f2tf32(v.x);
            As[(kq * 4 + 1) * PADA + m] = f2tf32(v.y);
            As[(kq * 4 + 2) * PADA + m] = f2tf32(v.z);
            As[(kq * 4 + 3) * PADA + m] = f2tf32(v.w);
        }
#pragma unroll
        for (int l = 0; l < 2; l++) {
            int idx = l * 256 + tid;
            int kk  = idx >> 5;
            int nq  = idx & 31;
            float4 v = *(const float4*)(Xb + (size_t)(k0 + kk) * N + n0 + nq * 4);
            uint4 t;
            t.x = f2tf32(v.x); t.y = f2tf32(v.y);
            t.z = f2tf32(v.z); t.w = f2tf32(v.w);
            *(uint4*)&Bs[kk * PADB + nq * 4] = t;
        }
        __syncthreads();

#pragma unroll
        for (int ks = 0; ks < 16; ks += 8) {
            uint32_t af[4][4];
#pragma unroll
            for (int mt = 0; mt < 4; mt++) {
                int mr = wm + mt * 16 + grp;
                int kc = ks + qid;
                af[mt][0] = As[kc * PADA + mr];
                af[mt][1] = As[kc * PADA + mr + 8];
                af[mt][2] = As[(kc + 4) * PADA + mr];
                af[mt][3] = As[(kc + 4) * PADA + mr + 8];
            }
            uint32_t bf[4][2];
#pragma unroll
            for (int nt = 0; nt < 4; nt++) {
                int nc = wn + nt * 8 + grp;
                int kr = ks + qid;
                bf[nt][0] = Bs[kr * PADB + nc];
                bf[nt][1] = Bs[(kr + 4) * PADB + nc];
            }
#pragma unroll
            for (int mt = 0; mt < 4; mt++)
#pragma unroll
                for (int nt = 0; nt < 4; nt++)
                    mma_tf32(acc[mt][nt], af[mt], bf[nt]);
        }
        __syncthreads();
    }

#pragma unroll
    for (int mt = 0; mt < 4; mt++) {
        const int r0 = m0 + wm + mt * 16 + grp;
        const int r1 = r0 + 8;
        const float bv0 = bias[r0];
        const float bv1 = bias[r1];
        const size_t rb0 = (size_t)b * M * N + (size_t)r0 * N;
        const size_t rb1 = (size_t)b * M * N + (size_t)r1 * N;
#pragma unroll
        for (int nt = 0; nt < 4; nt++) {
            const int col = n0 + wn + nt * 8 + 2 * qid;
            float2 v0 = make_float2(acc[mt][nt][0] + bv0, acc[mt][nt][1] + bv0);
            float2 v1 = make_float2(acc[mt][nt][2] + bv1, acc[mt][nt][3] + bv1);
            if (res) {
                const float2 q0 = *(const float2*)(res + rb0 + col);
                const float2 q1 = *(const float2*)(res + rb1 + col);
                v0.x += q0.x; v0.y += q0.y;
                v1.x += q1.x; v1.y += q1.y;
            }
            *(float2*)(C + rb0 + col) = v0;
            *(float2*)(C + rb1 + col) = v1;
        }
    }
}

// Fused Q/K/V projections: blockIdx.z = which*8 + b
__global__ __launch_bounds__(256) void mma_proj_qkv(
    const float* __restrict__ Wq, const float* __restrict__ bq,
    const float* __restrict__ Wk, const float* __restrict__ bk,
    const float* __restrict__ Wv, const float* __restrict__ bv,
    const float* __restrict__ self_f, const float* __restrict__ cross_f,
    float* __restrict__ gq, float* __restrict__ gk, float* __restrict__ gv)
{
    const int which = blockIdx.z >> 3;
    const int b     = blockIdx.z & 7;
    const float* A    = (which == 0) ? Wq : (which == 1) ? Wk : Wv;
    const float* bias = (which == 0) ? bq : (which == 1) ? bk : bv;
    const float* X    = (which == 0) ? self_f : cross_f;
    float*       C    = (which == 0) ? gq : (which == 1) ? gk : gv;
    mma_proj_body(A, X, bias, nullptr, C, b, blockIdx.y * 128, blockIdx.x * 128);
}

__global__ __launch_bounds__(256) void mma_proj_out(
    const float* __restrict__ A, const float* __restrict__ X,
    const float* __restrict__ bias, const float* __restrict__ res,
    float* __restrict__ C)
{
    mma_proj_body(A, X, bias, res, C, blockIdx.z, blockIdx.y * 128, blockIdx.x * 128);
}

// ---------------------------------------------------------------------------
// TF32 flash attention v2 (fixed cp.async tile coverage).
// Per (b,h): O^T = V^T P^T with P = softmax(Q K^T / 8).
// CTA: 128 q rows, 4 warps x 32 rows each (2 row-groups of 16).
// K-tile = 64 keys. K/V staged raw-fp32 via cp.async (mma truncates to tf32).
// ---------------------------------------------------------------------------
#define KS_ST 72
#define VS_ST 68

__global__ __launch_bounds__(128) void flash_mma2_kernel()
{
    const int N = 1024;
    const int b = blockIdx.z;
    const int h = blockIdx.y;
    const int tid  = threadIdx.x;
    const int lane = tid & 31;
    const int w    = tid >> 5;            // 0..3
    const int grp  = lane >> 2;
    const int qid  = lane & 3;
    const size_t base = ((size_t)b * CDIM + h * HDIM) * (size_t)N;
    const int q0 = blockIdx.x * 128 + w * 32;   // this warp's 32 q rows

    __shared__ uint32_t Ks[64 * KS_ST];
    __shared__ uint32_t Vs[64 * VS_ST];

    const uint32_t sKs = (uint32_t)__cvta_generic_to_shared(Ks);
    const uint32_t sVs = (uint32_t)__cvta_generic_to_shared(Vs);

    // ---- Q A-fragments for both row-groups (rna, scaled by 1/8)
    uint32_t qa[2][8][4];
#pragma unroll
    for (int g = 0; g < 2; g++) {
        const int r0 = q0 + g * 16 + grp;
#pragma unroll
        for (int kc = 0; kc < 8; kc++) {
            const int d0 = qid + 8 * kc;
            qa[g][kc][0] = f2tf32(g_q[base + (size_t)d0 * N + r0] * 0.125f);
            qa[g][kc][1] = f2tf32(g_q[base + (size_t)d0 * N + r0 + 8] * 0.125f);
            qa[g][kc][2] = f2tf32(g_q[base + (size_t)(d0 + 4) * N + r0] * 0.125f);
            qa[g][kc][3] = f2tf32(g_q[base + (size_t)(d0 + 4) * N + r0 + 8] * 0.125f);
        }
    }

    float o[4][4][4];        // [d-tile][q-col-tile][frag]
#pragma unroll
    for (int it = 0; it < 4; it++)
#pragma unroll
        for (int nj = 0; nj < 4; nj++)
#pragma unroll
            for (int r = 0; r < 4; r++) o[it][nj][r] = 0.f;
    float mx[2][2] = {{-1e30f, -1e30f}, {-1e30f, -1e30f}};
    float ll[2][2] = {{0.f, 0.f}, {0.f, 0.f}};

    for (int t0 = 0; t0 < N; t0 += 64) {
        // ---- stage K,V raw fp32: 64 rows x 64 floats = 16KB each.
        // 1024 chunks of 16B per tile: c in [0,1024), row = c>>4, ch = c&15.
#pragma unroll
        for (int i = 0; i < 8; i++) {
            const int c   = i * 128 + tid;
            const int row = c >> 4;
            const int ch  = c & 15;
            cp16(sKs + (row * KS_ST + ch * 4) * 4,
                 g_k + base + (size_t)row * N + t0 + ch * 4);
            cp16(sVs + (row * VS_ST + ch * 4) * 4,
                 g_v + base + (size_t)row * N + t0 + ch * 4);
        }
        cp_commit_wait();
        __syncthreads();

        // ---- S = Q K^T for both row groups (B-frags shared)
        float s[2][8][4];
#pragma unroll
        for (int g = 0; g < 2; g++)
#pragma unroll
            for (int nt = 0; nt < 8; nt++)
#pragma unroll
                for (int r = 0; r < 4; r++) s[g][nt][r] = 0.f;

#pragma unroll
        for (int nt = 0; nt < 8; nt++) {
#pragma unroll
            for (int kc = 0; kc < 8; kc++) {
                uint32_t bf[2];
                bf[0] = Ks[(kc * 8 + qid) * KS_ST + nt * 8 + grp];
                bf[1] = Ks[(kc * 8 + qid + 4) * KS_ST + nt * 8 + grp];
                mma_tf32(s[0][nt], qa[0][kc], bf);
                mma_tf32(s[1][nt], qa[1][kc], bf);
            }
        }

        // ---- online softmax per row-group
        uint32_t pu[2][8][4];
        float corr[2][2];
#pragma unroll
        for (int g = 0; g < 2; g++) {
            float t_0 = -1e30f, t_1 = -1e30f;
#pragma unroll
            for (int nt = 0; nt < 8; nt++) {
                t_0 = fmaxf(t_0, fmaxf(s[g][nt][0], s[g][nt][1]));
                t_1 = fmaxf(t_1, fmaxf(s[g][nt][2], s[g][nt][3]));
            }
            t_0 = fmaxf(t_0, __shfl_xor_sync(0xffffffffu, t_0, 1));
            t_0 = fmaxf(t_0, __shfl_xor_sync(0xffffffffu, t_0, 2));
            t_1 = fmaxf(t_1, __shfl_xor_sync(0xffffffffu, t_1, 1));
            t_1 = fmaxf(t_1, __shfl_xor_sync(0xffffffffu, t_1, 2));
            const float nm0 = fmaxf(mx[g][0], t_0);
            const float nm1 = fmaxf(mx[g][1], t_1);
            corr[g][0] = __expf(mx[g][0] - nm0);
            corr[g][1] = __expf(mx[g][1] - nm1);
            mx[g][0] = nm0; mx[g][1] = nm1;

            float rs0 = 0.f, rs1 = 0.f;
#pragma unroll
            for (int nt = 0; nt < 8; nt++) {
                float p0 = __expf(s[g][nt][0] - nm0);
                float p1 = __expf(s[g][nt][1] - nm0);
                float p2 = __expf(s[g][nt][2] - nm1);
                float p3 = __expf(s[g][nt][3] - nm1);
                rs0 += p0 + p1;
                rs1 += p2 + p3;
                pu[g][nt][0] = f2tf32(p0); pu[g][nt][1] = f2tf32(p1);
                pu[g][nt][2] = f2tf32(p2); pu[g][nt][3] = f2tf32(p3);
            }
            rs0 += __shfl_xor_sync(0xffffffffu, rs0, 1);
            rs0 += __shfl_xor_sync(0xffffffffu, rs0, 2);
            rs1 += __shfl_xor_sync(0xffffffffu, rs1, 1);
            rs1 += __shfl_xor_sync(0xffffffffu, rs1, 2);
            ll[g][0] = ll[g][0] * corr[g][0] + rs0;
            ll[g][1] = ll[g][1] * corr[g][1] + rs1;
        }

        // ---- rescale O^T: column q = nj*8 + 2*qid + t; factor from lane 8qid(+4)
        float cc[2][2][2];
#pragma unroll
        for (int g = 0; g < 2; g++)
#pragma unroll
            for (int p = 0; p < 2; p++) {
                cc[g][p][0] = __shfl_sync(0xffffffffu, corr[g][p], 8 * qid);
                cc[g][p][1] = __shfl_sync(0xffffffffu, corr[g][p], 8 * qid + 4);
            }
#pragma unroll
        for (int it = 0; it < 4; it++)
#pragma unroll
            for (int nj = 0; nj < 4; nj++) {
                const int g = nj >> 1, p = nj & 1;
                o[it][nj][0] *= cc[g][p][0];
                o[it][nj][1] *= cc[g][p][1];
                o[it][nj][2] *= cc[g][p][0];
                o[it][nj][3] *= cc[g][p][1];
            }

        // ---- O^T += V^T P^T
        const int srcA = (lane & ~3) | (qid >> 1);
        const int srcB = srcA + 2;
#pragma unroll
        for (int kc = 0; kc < 8; kc++) {
            uint32_t bj[4][2];
#pragma unroll
            for (int g = 0; g < 2; g++) {
                uint32_t a0 = __shfl_sync(0xffffffffu, pu[g][kc][0], srcA);
                uint32_t a1 = __shfl_sync(0xffffffffu, pu[g][kc][1], srcA);
                uint32_t a2 = __shfl_sync(0xffffffffu, pu[g][kc][2], srcA);
                uint32_t a3 = __shfl_sync(0xffffffffu, pu[g][kc][3], srcA);
                uint32_t b0 = __shfl_sync(0xffffffffu, pu[g][kc][0], srcB);
                uint32_t b1 = __shfl_sync(0xffffffffu, pu[g][kc][1], srcB);
                uint32_t b2 = __shfl_sync(0xffffffffu, pu[g][kc][2], srcB);
                uint32_t b3 = __shfl_sync(0xffffffffu, pu[g][kc][3], srcB);
                bj[g * 2 + 0][0] = (qid & 1) ? a1 : a0;
                bj[g * 2 + 0][1] = (qid & 1) ? b1 : b0;
                bj[g * 2 + 1][0] = (qid & 1) ? a3 : a2;
                bj[g * 2 + 1][1] = (qid & 1) ? b3 : b2;
            }
#pragma unroll
            for (int it = 0; it < 4; it++) {
                const int r = it * 16 + grp;
                uint32_t af[4];
                af[0] = Vs[r * VS_ST + kc * 8 + qid];
                af[1] = Vs[(r + 8) * VS_ST + kc * 8 + qid];
                af[2] = Vs[r * VS_ST + kc * 8 + qid + 4];
                af[3] = Vs[(r + 8) * VS_ST + kc * 8 + qid + 4];
                mma_tf32(o[it][0], af, bj[0]);
                mma_tf32(o[it][1], af, bj[1]);
                mma_tf32(o[it][2], af, bj[2]);
                mma_tf32(o[it][3], af, bj[3]);
            }
        }
        __syncthreads();
    }

    // ---- epilogue: divide by l per q-column, store O^T into [d][n] layout
    float iv[2][2][2];
#pragma unroll
    for (int g = 0; g < 2; g++)
#pragma unroll
        for (int p = 0; p < 2; p++) {
            iv[g][p][0] = 1.f / __shfl_sync(0xffffffffu, ll[g][p], 8 * qid);
            iv[g][p][1] = 1.f / __shfl_sync(0xffffffffu, ll[g][p], 8 * qid + 4);
        }
#pragma unroll
    for (int it = 0; it < 4; it++) {
        const int d0 = it * 16 + grp;
#pragma unroll
        for (int nj = 0; nj < 4; nj++) {
            const int g = nj >> 1, p = nj & 1;
            const int col = q0 + nj * 8 + 2 * qid;
            float2 v;
            v.x = o[it][nj][0] * iv[g][p][0];
            v.y = o[it][nj][1] * iv[g][p][1];
            *(float2*)&g_att[base + (size_t)d0 * N + col] = v;
            v.x = o[it][nj][2] * iv[g][p][0];
            v.y = o[it][nj][3] * iv[g][p][1];
            *(float2*)&g_att[base + (size_t)(d0 + 8) * N + col] = v;
        }
    }
}

// ---------------------------------------------------------------------------
extern "C" void kernel_launch(void* const* d_in, const int* in_sizes, int n_in,
                              void* d_out, int out_size)
{
    (void)in_sizes; (void)n_in; (void)out_size;
    const float* self_f  = (const float*)d_in[0];
    const float* cross_f = (const float*)d_in[1];
    const float* Wq   = (const float*)d_in[2];
    const float* bq   = (const float*)d_in[3];
    const float* Wk   = (const float*)d_in[4];
    const float* bk   = (const float*)d_in[5];
    const float* Wv   = (const float*)d_in[6];
    const float* bv   = (const float*)d_in[7];
    const float* Wout = (const float*)d_in[8];
    const float* bout = (const float*)d_in[9];
    float* out = (float*)d_out;

    float *gq, *gk, *gv, *ga;
    cudaGetSymbolAddress((void**)&gq, g_q);
    cudaGetSymbolAddress((void**)&gk, g_k);
    cudaGetSymbolAddress((void**)&gv, g_v);
    cudaGetSymbolAddress((void**)&ga, g_att);

    dim3 qkvGrid(NPIX / 128, CDIM / 128, 3 * BATCH);  // (8,4,24)
    mma_proj_qkv<<<qkvGrid, 256>>>(Wq, bq, Wk, bk, Wv, bv, self_f, cross_f,
                                   gq, gk, gv);

    dim3 attnGrid(NPIX / 128, HEADS, BATCH);          // (8,8,8)
    flash_mma2_kernel<<<attnGrid, 128>>>();

    dim3 outGrid(NPIX / 128, CDIM / 128, BATCH);      // (8,4,8)
    mma_proj_out<<<outGrid, 256>>>(Wout, ga, bout, self_f, out);
}

// round 7
// speedup vs baseline: 5.3520x; 1.2117x over previous
#include <cuda_runtime.h>
#include <cuda_bf16.h>
#include <math.h>
#include <stdint.h>

// Problem constants
#define BATCH 8
#define CDIM  512      // QUERY_DIM == CROSS_DIM == INNER
#define NPIX  1024     // H*W
#define HEADS 8
#define HDIM  64

// Scratch: q, k, v, attn_out  each [B, 512, 1024] fp32
__device__ float g_q[BATCH * CDIM * NPIX];
__device__ float g_k[BATCH * CDIM * NPIX];
__device__ float g_v[BATCH * CDIM * NPIX];
__device__ float g_att[BATCH * CDIM * NPIX];

__device__ __forceinline__ uint32_t f2tf32(float v) {
    uint32_t r;
    asm("cvt.rna.tf32.f32 %0, %1;" : "=r"(r) : "f"(v));
    return r;
}

__device__ __forceinline__ void mma_tf32(float c[4], const uint32_t a[4], const uint32_t b[2]) {
    asm volatile(
        "mma.sync.aligned.m16n8k8.row.col.f32.tf32.tf32.f32 "
        "{%0,%1,%2,%3}, {%4,%5,%6,%7}, {%8,%9}, {%0,%1,%2,%3};"
        : "+f"(c[0]), "+f"(c[1]), "+f"(c[2]), "+f"(c[3])
        : "r"(a[0]), "r"(a[1]), "r"(a[2]), "r"(a[3]), "r"(b[0]), "r"(b[1]));
}

__device__ __forceinline__ void cp16(uint32_t saddr, const void* gptr) {
    asm volatile("cp.async.ca.shared.global [%0], [%1], 16;" :: "r"(saddr), "l"(gptr));
}
__device__ __forceinline__ void cp_commit() {
    asm volatile("cp.async.commit_group;");
}
__device__ __forceinline__ void cp_wait1() {
    asm volatile("cp.async.wait_group 1;" ::: "memory");
}
__device__ __forceinline__ void cp_wait0() {
    asm volatile("cp.async.wait_group 0;" ::: "memory");
}

// ---------------------------------------------------------------------------
// TF32 tensor-core GEMM, double-buffered cp.async (raw fp32 -> hw tf32).
// C[b,m,n] = sum_k A[m,k] * X[b,k,n] + bias[m] (+res). M=512,K=512,N=1024.
// Block tile 128x128x16, 256 thr = 8 warps (2m x 4n), warp tile 64x32.
// A smem [m][k] stride 28 (28g+q bijective mod 32); B smem [k][n] stride 136
// (8q+g bijective). cp16 alignment: A row = 112B, B row = 544B, both 16B mult.
// ---------------------------------------------------------------------------
#define PA 28
#define PB 136

__device__ __forceinline__ void mma_proj_body(
    const float* __restrict__ A,
    const float* __restrict__ X,
    const float* __restrict__ bias,
    const float* __restrict__ res,
    float* __restrict__ C,
    int b, int m0, int n0)
{
    const int M = 512, K = 512, N = 1024;
    const float* Xb = X + (size_t)b * K * N;

    __shared__ uint32_t As[2 * 128 * PA];   // 28 KB
    __shared__ uint32_t Bs[2 * 16 * PB];    // 17 KB

    const uint32_t sA = (uint32_t)__cvta_generic_to_shared(As);
    const uint32_t sB = (uint32_t)__cvta_generic_to_shared(Bs);

    const int tid  = threadIdx.x;
    const int lane = tid & 31;
    const int wid  = tid >> 5;
    const int wm   = (wid >> 2) * 64;
    const int wn   = (wid & 3) * 32;
    const int grp  = lane >> 2;
    const int qid  = lane & 3;

    float acc[4][4][4];
#pragma unroll
    for (int i = 0; i < 4; i++)
#pragma unroll
        for (int j = 0; j < 4; j++)
#pragma unroll
            for (int r = 0; r < 4; r++) acc[i][j][r] = 0.f;

    // stage tile (k0, buffer p) via cp.async: 4 cp16 per thread
    auto issue_tile = [&](int k0, int p) {
#pragma unroll
        for (int i = 0; i < 2; i++) {           // A: 512 chunks
            const int c  = i * 256 + tid;
            const int r  = c >> 2;              // m row 0..127
            const int ch = c & 3;               // 16B chunk in k
            cp16(sA + ((p * 128 + r) * PA + ch * 4) * 4,
                 A + (size_t)(m0 + r) * K + k0 + ch * 4);
        }
#pragma unroll
        for (int i = 0; i < 2; i++) {           // B: 512 chunks
            const int c  = i * 256 + tid;
            const int r  = c >> 5;              // k row 0..15
            const int ch = c & 31;              // 16B chunk in n
            cp16(sB + ((p * 16 + r) * PB + ch * 4) * 4,
                 Xb + (size_t)(k0 + r) * N + n0 + ch * 4);
        }
        cp_commit();
    };

    issue_tile(0, 0);

    const int T = K / 16;                       // 32 tiles
    for (int t = 0; t < T; t++) {
        const int p = t & 1;
        if (t + 1 < T) { issue_tile((t + 1) * 16, (t + 1) & 1); cp_wait1(); }
        else          { cp_wait0(); }
        __syncthreads();

        const uint32_t* Ab = As + p * 128 * PA;
        const uint32_t* Bb = Bs + p * 16 * PB;

#pragma unroll
        for (int ks = 0; ks < 16; ks += 8) {
            uint32_t af[4][4];
#pragma unroll
            for (int mt = 0; mt < 4; mt++) {
                const int mr = wm + mt * 16 + grp;
                const int kc = ks + qid;
                af[mt][0] = Ab[mr * PA + kc];
                af[mt][1] = Ab[(mr + 8) * PA + kc];
                af[mt][2] = Ab[mr * PA + kc + 4];
                af[mt][3] = Ab[(mr + 8) * PA + kc + 4];
            }
            uint32_t bf[4][2];
#pragma unroll
            for (int nt = 0; nt < 4; nt++) {
                const int nc = wn + nt * 8 + grp;
                const int kr = ks + qid;
                bf[nt][0] = Bb[kr * PB + nc];
                bf[nt][1] = Bb[(kr + 4) * PB + nc];
            }
#pragma unroll
            for (int mt = 0; mt < 4; mt++)
#pragma unroll
                for (int nt = 0; nt < 4; nt++)
                    mma_tf32(acc[mt][nt], af[mt], bf[nt]);
        }
        __syncthreads();
    }

#pragma unroll
    for (int mt = 0; mt < 4; mt++) {
        const int r0 = m0 + wm + mt * 16 + grp;
        const int r1 = r0 + 8;
        const float bv0 = bias[r0];
        const float bv1 = bias[r1];
        const size_t rb0 = (size_t)b * M * N + (size_t)r0 * N;
        const size_t rb1 = (size_t)b * M * N + (size_t)r1 * N;
#pragma unroll
        for (int nt = 0; nt < 4; nt++) {
            const int col = n0 + wn + nt * 8 + 2 * qid;
            float2 v0 = make_float2(acc[mt][nt][0] + bv0, acc[mt][nt][1] + bv0);
            float2 v1 = make_float2(acc[mt][nt][2] + bv1, acc[mt][nt][3] + bv1);
            if (res) {
                const float2 q0 = *(const float2*)(res + rb0 + col);
                const float2 q1 = *(const float2*)(res + rb1 + col);
                v0.x += q0.x; v0.y += q0.y;
                v1.x += q1.x; v1.y += q1.y;
            }
            *(float2*)(C + rb0 + col) = v0;
            *(float2*)(C + rb1 + col) = v1;
        }
    }
}

// Fused Q/K/V projections: blockIdx.z = which*8 + b
__global__ __launch_bounds__(256) void mma_proj_qkv(
    const float* __restrict__ Wq, const float* __restrict__ bq,
    const float* __restrict__ Wk, const float* __restrict__ bk,
    const float* __restrict__ Wv, const float* __restrict__ bv,
    const float* __restrict__ self_f, const float* __restrict__ cross_f,
    float* __restrict__ gq, float* __restrict__ gk, float* __restrict__ gv)
{
    const int which = blockIdx.z >> 3;
    const int b     = blockIdx.z & 7;
    const float* A    = (which == 0) ? Wq : (which == 1) ? Wk : Wv;
    const float* bias = (which == 0) ? bq : (which == 1) ? bk : bv;
    const float* X    = (which == 0) ? self_f : cross_f;
    float*       C    = (which == 0) ? gq : (which == 1) ? gk : gv;
    mma_proj_body(A, X, bias, nullptr, C, b, blockIdx.y * 128, blockIdx.x * 128);
}

__global__ __launch_bounds__(256) void mma_proj_out(
    const float* __restrict__ A, const float* __restrict__ X,
    const float* __restrict__ bias, const float* __restrict__ res,
    float* __restrict__ C)
{
    mma_proj_body(A, X, bias, res, C, blockIdx.z, blockIdx.y * 128, blockIdx.x * 128);
}

// ---------------------------------------------------------------------------
// TF32 flash attention v2.
// Per (b,h): O^T = V^T P^T with P = softmax(Q K^T / 8).
// CTA: 128 q rows, 4 warps x 32 rows each (2 row-groups of 16).
// K-tile = 64 keys. K/V staged raw-fp32 via cp.async (mma truncates to tf32).
// ---------------------------------------------------------------------------
#define KS_ST 72
#define VS_ST 68

__global__ __launch_bounds__(128) void flash_mma2_kernel()
{
    const int N = 1024;
    const int b = blockIdx.z;
    const int h = blockIdx.y;
    const int tid  = threadIdx.x;
    const int lane = tid & 31;
    const int w    = tid >> 5;            // 0..3
    const int grp  = lane >> 2;
    const int qid  = lane & 3;
    const size_t base = ((size_t)b * CDIM + h * HDIM) * (size_t)N;
    const int q0 = blockIdx.x * 128 + w * 32;   // this warp's 32 q rows

    __shared__ uint32_t Ks[64 * KS_ST];
    __shared__ uint32_t Vs[64 * VS_ST];

    const uint32_t sKs = (uint32_t)__cvta_generic_to_shared(Ks);
    const uint32_t sVs = (uint32_t)__cvta_generic_to_shared(Vs);

    // ---- Q A-fragments for both row-groups (rna, scaled by 1/8)
    uint32_t qa[2][8][4];
#pragma unroll
    for (int g = 0; g < 2; g++) {
        const int r0 = q0 + g * 16 + grp;
#pragma unroll
        for (int kc = 0; kc < 8; kc++) {
            const int d0 = qid + 8 * kc;
            qa[g][kc][0] = f2tf32(g_q[base + (size_t)d0 * N + r0] * 0.125f);
            qa[g][kc][1] = f2tf32(g_q[base + (size_t)d0 * N + r0 + 8] * 0.125f);
            qa[g][kc][2] = f2tf32(g_q[base + (size_t)(d0 + 4) * N + r0] * 0.125f);
            qa[g][kc][3] = f2tf32(g_q[base + (size_t)(d0 + 4) * N + r0 + 8] * 0.125f);
        }
    }

    float o[4][4][4];        // [d-tile][q-col-tile][frag]
#pragma unroll
    for (int it = 0; it < 4; it++)
#pragma unroll
        for (int nj = 0; nj < 4; nj++)
#pragma unroll
            for (int r = 0; r < 4; r++) o[it][nj][r] = 0.f;
    float mx[2][2] = {{-1e30f, -1e30f}, {-1e30f, -1e30f}};
    float ll[2][2] = {{0.f, 0.f}, {0.f, 0.f}};

    for (int t0 = 0; t0 < N; t0 += 64) {
        // ---- stage K,V raw fp32: 64 rows x 64 floats = 16KB each.
#pragma unroll
        for (int i = 0; i < 8; i++) {
            const int c   = i * 128 + tid;
            const int row = c >> 4;
            const int ch  = c & 15;
            cp16(sKs + (row * KS_ST + ch * 4) * 4,
                 g_k + base + (size_t)row * N + t0 + ch * 4);
            cp16(sVs + (row * VS_ST + ch * 4) * 4,
                 g_v + base + (size_t)row * N + t0 + ch * 4);
        }
        cp_commit();
        cp_wait0();
        __syncthreads();

        // ---- S = Q K^T for both row groups (B-frags shared)
        float s[2][8][4];
#pragma unroll
        for (int g = 0; g < 2; g++)
#pragma unroll
            for (int nt = 0; nt < 8; nt++)
#pragma unroll
                for (int r = 0; r < 4; r++) s[g][nt][r] = 0.f;

#pragma unroll
        for (int nt = 0; nt < 8; nt++) {
#pragma unroll
            for (int kc = 0; kc < 8; kc++) {
                uint32_t bf[2];
                bf[0] = Ks[(kc * 8 + qid) * KS_ST + nt * 8 + grp];
                bf[1] = Ks[(kc * 8 + qid + 4) * KS_ST + nt * 8 + grp];
                mma_tf32(s[0][nt], qa[0][kc], bf);
                mma_tf32(s[1][nt], qa[1][kc], bf);
            }
        }

        // ---- online softmax per row-group
        uint32_t pu[2][8][4];
        float corr[2][2];
#pragma unroll
        for (int g = 0; g < 2; g++) {
            float t_0 = -1e30f, t_1 = -1e30f;
#pragma unroll
            for (int nt = 0; nt < 8; nt++) {
                t_0 = fmaxf(t_0, fmaxf(s[g][nt][0], s[g][nt][1]));
                t_1 = fmaxf(t_1, fmaxf(s[g][nt][2], s[g][nt][3]));
            }
            t_0 = fmaxf(t_0, __shfl_xor_sync(0xffffffffu, t_0, 1));
            t_0 = fmaxf(t_0, __shfl_xor_sync(0xffffffffu, t_0, 2));
            t_1 = fmaxf(t_1, __shfl_xor_sync(0xffffffffu, t_1, 1));
            t_1 = fmaxf(t_1, __shfl_xor_sync(0xffffffffu, t_1, 2));
            const float nm0 = fmaxf(mx[g][0], t_0);
            const float nm1 = fmaxf(mx[g][1], t_1);
            corr[g][0] = __expf(mx[g][0] - nm0);
            corr[g][1] = __expf(mx[g][1] - nm1);
            mx[g][0] = nm0; mx[g][1] = nm1;

            float rs0 = 0.f, rs1 = 0.f;
#pragma unroll
            for (int nt = 0; nt < 8; nt++) {
                float p0 = __expf(s[g][nt][0] - nm0);
                float p1 = __expf(s[g][nt][1] - nm0);
                float p2 = __expf(s[g][nt][2] - nm1);
                float p3 = __expf(s[g][nt][3] - nm1);
                rs0 += p0 + p1;
                rs1 += p2 + p3;
                pu[g][nt][0] = f2tf32(p0); pu[g][nt][1] = f2tf32(p1);
                pu[g][nt][2] = f2tf32(p2); pu[g][nt][3] = f2tf32(p3);
            }
            rs0 += __shfl_xor_sync(0xffffffffu, rs0, 1);
            rs0 += __shfl_xor_sync(0xffffffffu, rs0, 2);
            rs1 += __shfl_xor_sync(0xffffffffu, rs1, 1);
            rs1 += __shfl_xor_sync(0xffffffffu, rs1, 2);
            ll[g][0] = ll[g][0] * corr[g][0] + rs0;
            ll[g][1] = ll[g][1] * corr[g][1] + rs1;
        }

        // ---- rescale O^T
        float cc[2][2][2];
#pragma unroll
        for (int g = 0; g < 2; g++)
#pragma unroll
            for (int p = 0; p < 2; p++) {
                cc[g][p][0] = __shfl_sync(0xffffffffu, corr[g][p], 8 * qid);
                cc[g][p][1] = __shfl_sync(0xffffffffu, corr[g][p], 8 * qid + 4);
            }
#pragma unroll
        for (int it = 0; it < 4; it++)
#pragma unroll
            for (int nj = 0; nj < 4; nj++) {
                const int g = nj >> 1, p = nj & 1;
                o[it][nj][0] *= cc[g][p][0];
                o[it][nj][1] *= cc[g][p][1];
                o[it][nj][2] *= cc[g][p][0];
                o[it][nj][3] *= cc[g][p][1];
            }

        // ---- O^T += V^T P^T
        const int srcA = (lane & ~3) | (qid >> 1);
        const int srcB = srcA + 2;
#pragma unroll
        for (int kc = 0; kc < 8; kc++) {
            uint32_t bj[4][2];
#pragma unroll
            for (int g = 0; g < 2; g++) {
                uint32_t a0 = __shfl_sync(0xffffffffu, pu[g][kc][0], srcA);
                uint32_t a1 = __shfl_sync(0xffffffffu, pu[g][kc][1], srcA);
                uint32_t a2 = __shfl_sync(0xffffffffu, pu[g][kc][2], srcA);
                uint32_t a3 = __shfl_sync(0xffffffffu, pu[g][kc][3], srcA);
                uint32_t b0 = __shfl_sync(0xffffffffu, pu[g][kc][0], srcB);
                uint32_t b1 = __shfl_sync(0xffffffffu, pu[g][kc][1], srcB);
                uint32_t b2 = __shfl_sync(0xffffffffu, pu[g][kc][2], srcB);
                uint32_t b3 = __shfl_sync(0xffffffffu, pu[g][kc][3], srcB);
                bj[g * 2 + 0][0] = (qid & 1) ? a1 : a0;
                bj[g * 2 + 0][1] = (qid & 1) ? b1 : b0;
                bj[g * 2 + 1][0] = (qid & 1) ? a3 : a2;
                bj[g * 2 + 1][1] = (qid & 1) ? b3 : b2;
            }
#pragma unroll
            for (int it = 0; it < 4; it++) {
                const int r = it * 16 + grp;
                uint32_t af[4];
                af[0] = Vs[r * VS_ST + kc * 8 + qid];
                af[1] = Vs[(r + 8) * VS_ST + kc * 8 + qid];
                af[2] = Vs[r * VS_ST + kc * 8 + qid + 4];
                af[3] = Vs[(r + 8) * VS_ST + kc * 8 + qid + 4];
                mma_tf32(o[it][0], af, bj[0]);
                mma_tf32(o[it][1], af, bj[1]);
                mma_tf32(o[it][2], af, bj[2]);
                mma_tf32(o[it][3], af, bj[3]);
            }
        }
        __syncthreads();
    }

    // ---- epilogue
    float iv[2][2][2];
#pragma unroll
    for (int g = 0; g < 2; g++)
#pragma unroll
        for (int p = 0; p < 2; p++) {
            iv[g][p][0] = 1.f / __shfl_sync(0xffffffffu, ll[g][p], 8 * qid);
            iv[g][p][1] = 1.f / __shfl_sync(0xffffffffu, ll[g][p], 8 * qid + 4);
        }
#pragma unroll
    for (int it = 0; it < 4; it++) {
        const int d0 = it * 16 + grp;
#pragma unroll
        for (int nj = 0; nj < 4; nj++) {
            const int g = nj >> 1, p = nj & 1;
            const int col = q0 + nj * 8 + 2 * qid;
            float2 v;
            v.x = o[it][nj][0] * iv[g][p][0];
            v.y = o[it][nj][1] * iv[g][p][1];
            *(float2*)&g_att[base + (size_t)d0 * N + col] = v;
            v.x = o[it][nj][2] * iv[g][p][0];
            v.y = o[it][nj][3] * iv[g][p][1];
            *(float2*)&g_att[base + (size_t)(d0 + 8) * N + col] = v;
        }
    }
}

// ---------------------------------------------------------------------------
extern "C" void kernel_launch(void* const* d_in, const int* in_sizes, int n_in,
                              void* d_out, int out_size)
{
    (void)in_sizes; (void)n_in; (void)out_size;
    const float* self_f  = (const float*)d_in[0];
    const float* cross_f = (const float*)d_in[1];
    const float* Wq   = (const float*)d_in[2];
    const float* bq   = (const float*)d_in[3];
    const float* Wk   = (const float*)d_in[4];
    const float* bk   = (const float*)d_in[5];
    const float* Wv   = (const float*)d_in[6];
    const float* bv   = (const float*)d_in[7];
    const float* Wout = (const float*)d_in[8];
    const float* bout = (const float*)d_in[9];
    float* out = (float*)d_out;

    float *gq, *gk, *gv, *ga;
    cudaGetSymbolAddress((void**)&gq, g_q);
    cudaGetSymbolAddress((void**)&gk, g_k);
    cudaGetSymbolAddress((void**)&gv, g_v);
    cudaGetSymbolAddress((void**)&ga, g_att);

    dim3 qkvGrid(NPIX / 128, CDIM / 128, 3 * BATCH);  // (8,4,24)
    mma_proj_qkv<<<qkvGrid, 256>>>(Wq, bq, Wk, bk, Wv, bv, self_f, cross_f,
                                   gq, gk, gv);

    dim3 attnGrid(NPIX / 128, HEADS, BATCH);          // (8,8,8)
    flash_mma2_kernel<<<attnGrid, 128>>>();

    dim3 outGrid(NPIX / 128, CDIM / 128, BATCH);      // (8,4,8)
    mma_proj_out<<<outGrid, 256>>>(Wout, ga, bout, self_f, out);
}